// round 2
// baseline (speedup 1.0000x reference)
#include <cuda_runtime.h>
#include <cuda_bf16.h>
#include <cstddef>

// ---------------------------------------------------------------------------
// Problem constants
// ---------------------------------------------------------------------------
#define N_NODES 100
#define IN_C    65536
#define OUT_C   60
#define N_EDGES 1600
#define NCOLS   360          // 2 heads * 3 cheb orders * 60
#define NSPLIT  96           // K-splits for the big GEMM

typedef unsigned long long u64;

__device__ __forceinline__ u64 pack2(float lo, float hi) {
    u64 r; asm("mov.b64 %0, {%1, %2};" : "=l"(r) : "f"(lo), "f"(hi)); return r;
}
__device__ __forceinline__ void ffma2(u64 &d, u64 a, u64 b) {
    asm("fma.rn.f32x2 %0, %1, %2, %0;" : "+l"(d) : "l"(a), "l"(b));
}
__device__ __forceinline__ void unpack2(float &lo, float &hi, u64 v) {
    asm("mov.b64 {%0, %1}, %2;" : "=f"(lo), "=f"(hi) : "l"(v));
}

// ---------------------------------------------------------------------------
// Scratch (no cudaMalloc allowed)
// ---------------------------------------------------------------------------
__device__ float g_A[N_NODES * N_NODES];     // dense normalized adjacency (Â)
__device__ float g_Y[N_NODES * NCOLS];       // x @ Wcat   [100, 360]
__device__ float g_U[N_NODES * 120];         // (Â @ Y2), layout [node][120] (h*60+c)
__device__ float g_emb[2 * N_NODES * OUT_C]; // final embeddings per head
__device__ float g_V[2 * OUT_C];             // vnr sums per head

// ---------------------------------------------------------------------------
// Kernel 1: prep — zero Y/A, build Â from edges, vnr sums, init outputs w/ bias
// ---------------------------------------------------------------------------
__global__ void prep_kernel(const int* __restrict__ ei,
                            const float* __restrict__ vnr,
                            const float* __restrict__ avw, const float* __restrict__ avb,
                            const float* __restrict__ cvw, const float* __restrict__ cvb,
                            const float* __restrict__ afb, const float* __restrict__ cfb,
                            float* __restrict__ out, int out_size) {
    __shared__ float sdeg[N_NODES];
    const int t = threadIdx.x;  // 256 threads

    for (int i = t; i < N_NODES * NCOLS; i += 256) g_Y[i] = 0.f;
    for (int i = t; i < N_NODES * N_NODES; i += 256) g_A[i] = 0.f;
    if (t < N_NODES) sdeg[t] = 0.f;
    __syncthreads();

    for (int e = t; e < N_EDGES; e += 256) atomicAdd(&sdeg[ei[e]], 1.f);
    __syncthreads();
    if (t < N_NODES) {
        float d = sdeg[t];
        sdeg[t] = (d > 0.f) ? rsqrtf(fmaxf(d, 1.f)) : 0.f;
    }
    __syncthreads();

    for (int e = t; e < N_EDGES; e += 256) {
        int s = ei[e];
        int d = ei[N_EDGES + e];
        atomicAdd(&g_A[d * N_NODES + s], -sdeg[s] * sdeg[d]);
    }

    if (t < OUT_C) {
        float va = 0.f, vc = 0.f;
        #pragma unroll
        for (int i = 0; i < 3; i++) {
            float v = vnr[i];
            va += v * avw[i * OUT_C + t] + avb[i * OUT_C + t];
            vc += v * cvw[i * OUT_C + t] + cvb[i * OUT_C + t];
        }
        g_V[t] = va;
        g_V[OUT_C + t] = vc;
    }

    for (int j = t; j < out_size; j += 256)
        out[j] = (j < 100) ? afb[j] : ((j == 100) ? cfb[0] : 0.f);
}

// ---------------------------------------------------------------------------
// Kernel 2: fused GEMM  Y[100,360] = x[100,65536] @ Wcat[65536,360]
//   f32x2 packed FMA; x pre-duplicated (x,x) in smem so inner loop has no packs
//   Block tile: 100m x 128n, split-K (96), 320 threads, thread tile 5m x 8n
// ---------------------------------------------------------------------------
__global__ __launch_bounds__(320, 2)
void gemm_kernel(const float* __restrict__ x,
                 const float* __restrict__ aw,
                 const float* __restrict__ cw) {
    __shared__ u64   xs2[N_NODES][36];       // [m][k] duplicated pairs (28.8 KB)
    __shared__ float ws[32][132];            // [k][n] (16.9 KB)
    __shared__ const float* wptr[128];

    const int t  = threadIdx.x;
    const int tx = t & 15;       // n-group 0..15
    const int ty = t >> 4;       // m-group 0..19
    const int nb0 = blockIdx.x * 128;

    int k0 = (int)(((long long)blockIdx.y * IN_C) / NSPLIT) & ~3;
    int k1 = (int)(((long long)(blockIdx.y + 1) * IN_C) / NSPLIT) & ~3;

    if (t < 128) {
        int col = nb0 + t;
        const float* p = nullptr;
        if (col < NCOLS) {
            int h  = col / 180;
            int r  = col % 180;
            int kk = r / OUT_C;
            int ch = r % OUT_C;
            p = (h ? cw : aw) + (size_t)kk * IN_C * OUT_C + ch;
        }
        wptr[t] = p;
    }

    u64 acc[5][4];
    #pragma unroll
    for (int i = 0; i < 5; i++)
        #pragma unroll
        for (int j = 0; j < 4; j++) acc[i][j] = 0ull;

    __syncthreads();

    for (int kp = k0; kp < k1; kp += 32) {
        const int klen = min(32, k1 - kp);      // multiple of 4
        const int kq = klen >> 2;

        // ---- x tile: load float4, store duplicated pairs
        for (int l = t; l < N_NODES * 8; l += 320) {
            int m = l >> 3, k4 = l & 7;
            if (k4 < kq) {
                float4 v = *(const float4*)(x + (size_t)m * IN_C + kp + (k4 << 2));
                int kk = k4 << 2;
                xs2[m][kk + 0] = pack2(v.x, v.x);
                xs2[m][kk + 1] = pack2(v.y, v.y);
                xs2[m][kk + 2] = pack2(v.z, v.z);
                xs2[m][kk + 3] = pack2(v.w, v.w);
            }
        }
        // ---- w tile [klen][128]
        for (int l = t; l < 32 * 128; l += 320) {
            int n = l & 127, k = l >> 7;
            float v = 0.f;
            const float* p = wptr[n];
            if (p != nullptr && k < klen) v = p[(size_t)(kp + k) * OUT_C];
            ws[k][n] = v;
        }
        __syncthreads();

        #pragma unroll 4
        for (int k = 0; k < klen; k++) {
            // w pairs: reinterpret the two 16B vectors as 4 packed f32x2
            double2 w0 = *(const double2*)&ws[k][tx * 8];
            double2 w1 = *(const double2*)&ws[k][tx * 8 + 4];
            u64 wb[4];
            wb[0] = __double_as_longlong(w0.x);
            wb[1] = __double_as_longlong(w0.y);
            wb[2] = __double_as_longlong(w1.x);
            wb[3] = __double_as_longlong(w1.y);
            #pragma unroll
            for (int i = 0; i < 5; i++) {
                u64 xv = xs2[ty * 5 + i][k];
                #pragma unroll
                for (int j = 0; j < 4; j++)
                    ffma2(acc[i][j], xv, wb[j]);
            }
        }
        __syncthreads();
    }

    // ---- split-K reduction
    #pragma unroll
    for (int i = 0; i < 5; i++) {
        int m = ty * 5 + i;
        #pragma unroll
        for (int j = 0; j < 4; j++) {
            float lo, hi;
            unpack2(lo, hi, acc[i][j]);
            int n = nb0 + tx * 8 + 2 * j;
            if (n < NCOLS)     atomicAdd(&g_Y[m * NCOLS + n], lo);
            if (n + 1 < NCOLS) atomicAdd(&g_Y[m * NCOLS + n + 1], hi);
        }
    }
}

// ---------------------------------------------------------------------------
// Kernel 3: U[m][h*60+c] = (Â @ Y2)[m, h, c].  grid 100, 128 threads.
// Row-coalesced: Â row in smem, Y rows read coalesced from L2.
// ---------------------------------------------------------------------------
__global__ void u2_kernel() {
    __shared__ float Arow[N_NODES];
    const int m = blockIdx.x, t = threadIdx.x;
    if (t < N_NODES) Arow[t] = g_A[m * N_NODES + t];
    __syncthreads();
    if (t >= 120) return;
    const int h = t / OUT_C, c = t % OUT_C;
    const float* Ycol = g_Y + h * 180 + 120 + c;   // Y2 column
    float acc = 0.f;
    #pragma unroll 10
    for (int s = 0; s < N_NODES; s++)
        acc = fmaf(Arow[s], Ycol[s * NCOLS], acc);
    g_U[m * 120 + t] = acc;
}

// ---------------------------------------------------------------------------
// Kernel 4: emb = tanh(Y0 - Y2 + Â@(Y1 + 2U) + cheb_b) + vnr_sum
// grid 100, 128 threads; U reads fully coalesced.
// ---------------------------------------------------------------------------
__global__ void v2_kernel(const float* __restrict__ acb,
                          const float* __restrict__ ccb) {
    __shared__ float Arow[N_NODES];
    const int m = blockIdx.x, t = threadIdx.x;
    if (t < N_NODES) Arow[t] = g_A[m * N_NODES + t];
    __syncthreads();
    if (t >= 120) return;
    const int h = t / OUT_C, c = t % OUT_C;
    const float* Y1col = g_Y + h * 180 + 60 + c;
    const float* Ucol  = g_U + t;
    float acc = 0.f;
    #pragma unroll 10
    for (int s = 0; s < N_NODES; s++)
        acc = fmaf(Arow[s], fmaf(2.f, Ucol[s * 120], Y1col[s * NCOLS]), acc);
    const float* Yr = g_Y + m * NCOLS + h * 180;
    float pre = Yr[c] - Yr[120 + c] + acc + (h ? ccb[c] : acb[c]);
    g_emb[h * N_NODES * OUT_C + m * OUT_C + c] = tanhf(pre) + g_V[h * OUT_C + c];
}

// ---------------------------------------------------------------------------
// Kernel 5: heads.  24 blocks x 128 threads, 250 rows each of the 6000-dot
// ---------------------------------------------------------------------------
__global__ void fc_kernel(const float* __restrict__ afw,
                          const float* __restrict__ cfw,
                          float* __restrict__ out, int out_size) {
    __shared__ float ea[250], ec[250];
    __shared__ float red[4];
    const int b = blockIdx.x, t = threadIdx.x;
    const int i0 = b * 250;

    for (int i = t; i < 250; i += 128) {
        ea[i] = g_emb[i0 + i];
        ec[i] = g_emb[6000 + i0 + i];
    }
    __syncthreads();

    if (t < 100) {
        float acc = 0.f;
        #pragma unroll 5
        for (int i = 0; i < 250; i++)
            acc = fmaf(ea[i], afw[(size_t)(i0 + i) * 100 + t], acc);
        atomicAdd(&out[t], acc);
    }

    float cacc = 0.f;
    for (int i = t; i < 250; i += 128) cacc = fmaf(ec[i], cfw[i0 + i], cacc);
    #pragma unroll
    for (int off = 16; off > 0; off >>= 1)
        cacc += __shfl_down_sync(0xffffffffu, cacc, off);
    if ((t & 31) == 0) red[t >> 5] = cacc;
    __syncthreads();
    if (t == 0 && out_size > 100)
        atomicAdd(&out[100], red[0] + red[1] + red[2] + red[3]);
}

// ---------------------------------------------------------------------------
// Launch
// ---------------------------------------------------------------------------
extern "C" void kernel_launch(void* const* d_in, const int* in_sizes, int n_in,
                              void* d_out, int out_size) {
    const float* x   = (const float*)d_in[0];
    const int*   ei  = (const int*)  d_in[1];
    const float* vnr = (const float*)d_in[2];
    const float* aw  = (const float*)d_in[3];
    const float* acb = (const float*)d_in[4];
    const float* cw  = (const float*)d_in[5];
    const float* ccb = (const float*)d_in[6];
    const float* avw = (const float*)d_in[7];
    const float* avb = (const float*)d_in[8];
    const float* cvw = (const float*)d_in[9];
    const float* cvb = (const float*)d_in[10];
    const float* afw = (const float*)d_in[11];
    const float* afb = (const float*)d_in[12];
    const float* cfw = (const float*)d_in[13];
    const float* cfb = (const float*)d_in[14];
    float* out = (float*)d_out;

    prep_kernel<<<1, 256>>>(ei, vnr, avw, avb, cvw, cvb, afb, cfb, out, out_size);
    gemm_kernel<<<dim3(3, NSPLIT), 320>>>(x, aw, cw);
    u2_kernel<<<N_NODES, 128>>>();
    v2_kernel<<<N_NODES, 128>>>(acb, ccb);
    fc_kernel<<<24, 128>>>(afw, cfw, out, out_size);
}

// round 4
// speedup vs baseline: 2.2983x; 2.2983x over previous
#include <cuda_runtime.h>
#include <cuda_bf16.h>
#include <cstdint>
#include <cstddef>

// ---------------------------------------------------------------------------
// Problem constants
// ---------------------------------------------------------------------------
#define N_NODES 100
#define IN_C    65536
#define OUT_C   60
#define N_EDGES 1600
#define NSPLIT  24
#define KTILE   64
#define GTHREADS 256

typedef unsigned int u32;

// ---------------------------------------------------------------------------
// smem word-layout constants (per stage, in 32-bit words)
//   A tiles: 128 rows x 72 bf16 (36 words/row) = 4608 words
//   B tiles:  64 rows x 72 bf16             = 2304 words
// ---------------------------------------------------------------------------
#define AROW_W  36
#define AHI_W   0
#define ALO_W   4608
#define BHI_W   9216
#define BLO_W   11520
#define STAGE_W 13824
#define SMEM_W  (2 * STAGE_W)
#define SMEM_B  (SMEM_W * 4)

__device__ __forceinline__ u32 bfpack2(float lo, float hi) {
    __nv_bfloat162 p = __floats2bfloat162_rn(lo, hi);
    return *(u32*)&p;
}

// mma.sync m16n8k16 row.col f32.bf16.bf16.f32
__device__ __forceinline__ void mma16816(float* c, const u32* a, const u32* b) {
    asm volatile(
        "mma.sync.aligned.m16n8k16.row.col.f32.bf16.bf16.f32 "
        "{%0,%1,%2,%3}, {%4,%5,%6,%7}, {%8,%9}, {%0,%1,%2,%3};"
        : "+f"(c[0]), "+f"(c[1]), "+f"(c[2]), "+f"(c[3])
        : "r"(a[0]), "r"(a[1]), "r"(a[2]), "r"(a[3]), "r"(b[0]), "r"(b[1]));
}

// ---------------------------------------------------------------------------
// Scratch
// ---------------------------------------------------------------------------
__device__ float g_Yt[360 * 100];   // transposed Y: [col][node]
__device__ float g_A[10000];        // normalized adjacency (Â)
__device__ float g_emb[2 * 6000];
__device__ float g_V[120];

// ---------------------------------------------------------------------------
// Kernel 1: prep — Â, vnr sums, zero Yt, init out with biases
// ---------------------------------------------------------------------------
__global__ void prep_kernel(const int* __restrict__ ei,
                            const float* __restrict__ vnr,
                            const float* __restrict__ avw, const float* __restrict__ avb,
                            const float* __restrict__ cvw, const float* __restrict__ cvb,
                            const float* __restrict__ afb, const float* __restrict__ cfb,
                            float* __restrict__ out, int out_size) {
    __shared__ float sA[10000];
    __shared__ float sdeg[N_NODES];
    const int t = threadIdx.x;  // 1024

    for (int i = t; i < 360 * 100; i += 1024) g_Yt[i] = 0.f;
    for (int i = t; i < 10000; i += 1024) sA[i] = 0.f;
    if (t < N_NODES) sdeg[t] = 0.f;
    __syncthreads();

    for (int e = t; e < N_EDGES; e += 1024) atomicAdd(&sdeg[ei[e]], 1.f);
    __syncthreads();
    if (t < N_NODES) {
        float d = sdeg[t];
        sdeg[t] = (d > 0.f) ? rsqrtf(fmaxf(d, 1.f)) : 0.f;
    }
    __syncthreads();
    for (int e = t; e < N_EDGES; e += 1024) {
        int s = ei[e];
        int d = ei[N_EDGES + e];
        atomicAdd(&sA[d * N_NODES + s], -sdeg[s] * sdeg[d]);
    }
    __syncthreads();
    for (int i = t; i < 10000; i += 1024) g_A[i] = sA[i];

    if (t < OUT_C) {
        float va = 0.f, vc = 0.f;
        #pragma unroll
        for (int i = 0; i < 3; i++) {
            float v = vnr[i];
            va += v * avw[i * OUT_C + t] + avb[i * OUT_C + t];
            vc += v * cvw[i * OUT_C + t] + cvb[i * OUT_C + t];
        }
        g_V[t] = va;
        g_V[OUT_C + t] = vc;
    }

    for (int j = t; j < out_size; j += 1024)
        out[j] = (j < 100) ? afb[j] : ((j == 100) ? cfb[0] : 0.f);
}

// ---------------------------------------------------------------------------
// Kernel 2: bf16-split tensor-core GEMM via mma.sync (portable HMMA)
//   grid (NSPLIT, 6); block 256 thr = 8 warps (4 m-warps x 2 n-warps)
//   Yt[col][node] += (x @ W_group)  with hi/lo bf16 split, fp32 accum
// ---------------------------------------------------------------------------
__global__ __launch_bounds__(GTHREADS, 1)
void gemm_mma(const float* __restrict__ x,
              const float* __restrict__ aw,
              const float* __restrict__ cw) {
    extern __shared__ u32 smw[];
    const int t = threadIdx.x;
    const int lane = t & 31, wid = t >> 5;
    const int wm = wid >> 1, wn = wid & 1;
    const int hk = blockIdx.y;                 // h*3 + kk
    const float* Wbase = ((hk >= 3) ? cw : aw) + (size_t)(hk % 3) * IN_C * OUT_C;

    int k0 = (int)(((long long)blockIdx.x * IN_C) / NSPLIT) & ~(KTILE - 1);
    int k1 = (int)(((long long)(blockIdx.x + 1) * IN_C) / NSPLIT) & ~(KTILE - 1);
    const int nch = (k1 - k0) / KTILE;

    // zero both stages once (padded rows stay zero)
    for (int i = t; i < SMEM_W; i += GTHREADS) smw[i] = 0;

    float acc[2][4][4];
    #pragma unroll
    for (int mt = 0; mt < 2; mt++)
        #pragma unroll
        for (int nt = 0; nt < 4; nt++)
            #pragma unroll
            for (int q = 0; q < 4; q++) acc[mt][nt][q] = 0.f;

    // ---- prefetch registers
    float4 xr[7];
    float  wr[15];
    {
        int kb = k0;
        #pragma unroll
        for (int i = 0; i < 7; i++) {
            int idx = t + i * GTHREADS;
            if (idx < 1600) {
                int m = idx >> 4, k4 = idx & 15;
                xr[i] = *(const float4*)(x + (size_t)m * IN_C + kb + (k4 << 2));
            }
        }
        #pragma unroll
        for (int i = 0; i < 15; i++) {
            int idx = t + i * GTHREADS;
            int k = idx / OUT_C, ch = idx - k * OUT_C;
            wr[i] = Wbase[(size_t)(kb + k) * OUT_C + ch];
        }
    }
    __syncthreads();

    for (int c = 0; c < nch; c++) {
        u32* sb = smw + (c & 1) * STAGE_W;

        // ---- convert prefetched regs -> bf16 hi/lo smem tiles
        #pragma unroll
        for (int i = 0; i < 7; i++) {
            int idx = t + i * GTHREADS;
            if (idx < 1600) {
                int m = idx >> 4, k4 = idx & 15;
                float4 v = xr[i];
                u32 h01 = bfpack2(v.x, v.y), h23 = bfpack2(v.z, v.w);
                float f0 = __uint_as_float(h01 << 16);
                float f1 = __uint_as_float(h01 & 0xffff0000u);
                float f2 = __uint_as_float(h23 << 16);
                float f3 = __uint_as_float(h23 & 0xffff0000u);
                u32 l01 = bfpack2(v.x - f0, v.y - f1);
                u32 l23 = bfpack2(v.z - f2, v.w - f3);
                int wofs = m * AROW_W + k4 * 2;
                sb[AHI_W + wofs] = h01; sb[AHI_W + wofs + 1] = h23;
                sb[ALO_W + wofs] = l01; sb[ALO_W + wofs + 1] = l23;
            }
        }
        #pragma unroll
        for (int i = 0; i < 15; i++) {
            int idx = t + i * GTHREADS;
            int k = idx / OUT_C, ch = idx - k * OUT_C;
            float w = wr[i];
            __nv_bfloat16 wh = __float2bfloat16(w);
            float whf = __uint_as_float(((u32)*(unsigned short*)&wh) << 16);
            __nv_bfloat16 wl = __float2bfloat16(w - whf);
            ((__nv_bfloat16*)(sb + BHI_W))[ch * 72 + k] = wh;
            ((__nv_bfloat16*)(sb + BLO_W))[ch * 72 + k] = wl;
        }
        __syncthreads();

        // ---- prefetch next stage
        if (c + 1 < nch) {
            int kb = k0 + (c + 1) * KTILE;
            #pragma unroll
            for (int i = 0; i < 7; i++) {
                int idx = t + i * GTHREADS;
                if (idx < 1600) {
                    int m = idx >> 4, k4 = idx & 15;
                    xr[i] = *(const float4*)(x + (size_t)m * IN_C + kb + (k4 << 2));
                }
            }
            #pragma unroll
            for (int i = 0; i < 15; i++) {
                int idx = t + i * GTHREADS;
                int k = idx / OUT_C, ch = idx - k * OUT_C;
                wr[i] = Wbase[(size_t)(kb + k) * OUT_C + ch];
            }
        }

        // ---- 4 x (k16) mma steps on this stage
        const int r = lane >> 2, kq = lane & 3;
        #pragma unroll
        for (int kc = 0; kc < 4; kc++) {
            const int kw = kc * 8 + kq;
            u32 ah[2][4], al[2][4], bh[4][2], bl[4][2];
            #pragma unroll
            for (int mt = 0; mt < 2; mt++) {
                int rw = (wm * 32 + mt * 16 + r) * AROW_W;
                ah[mt][0] = sb[AHI_W + rw + kw];
                ah[mt][1] = sb[AHI_W + rw + 8 * AROW_W + kw];
                ah[mt][2] = sb[AHI_W + rw + kw + 4];
                ah[mt][3] = sb[AHI_W + rw + 8 * AROW_W + kw + 4];
                al[mt][0] = sb[ALO_W + rw + kw];
                al[mt][1] = sb[ALO_W + rw + 8 * AROW_W + kw];
                al[mt][2] = sb[ALO_W + rw + kw + 4];
                al[mt][3] = sb[ALO_W + rw + 8 * AROW_W + kw + 4];
            }
            #pragma unroll
            for (int nt = 0; nt < 4; nt++) {
                int nw = (wn * 32 + nt * 8 + r) * AROW_W;
                bh[nt][0] = sb[BHI_W + nw + kw];
                bh[nt][1] = sb[BHI_W + nw + kw + 4];
                bl[nt][0] = sb[BLO_W + nw + kw];
                bl[nt][1] = sb[BLO_W + nw + kw + 4];
            }
            #pragma unroll
            for (int mt = 0; mt < 2; mt++)
                #pragma unroll
                for (int nt = 0; nt < 4; nt++) {
                    mma16816(acc[mt][nt], ah[mt], bh[nt]);
                    mma16816(acc[mt][nt], ah[mt], bl[nt]);
                    mma16816(acc[mt][nt], al[mt], bh[nt]);
                }
        }
        __syncthreads();
    }

    // ---- epilogue: atomicAdd into transposed Yt
    const int r = lane >> 2, cb = (lane & 3) * 2;
    float* Yg = g_Yt + hk * 60 * 100;
    #pragma unroll
    for (int mt = 0; mt < 2; mt++) {
        int row = wm * 32 + mt * 16 + r;
        #pragma unroll
        for (int nt = 0; nt < 4; nt++) {
            int col = wn * 32 + nt * 8 + cb;
            if (col < OUT_C) {
                if (row < N_NODES)     atomicAdd(Yg + col * 100 + row,     acc[mt][nt][0]);
                if (row + 8 < N_NODES) atomicAdd(Yg + col * 100 + row + 8, acc[mt][nt][2]);
            }
            if (col + 1 < OUT_C) {
                if (row < N_NODES)     atomicAdd(Yg + (col + 1) * 100 + row,     acc[mt][nt][1]);
                if (row + 8 < N_NODES) atomicAdd(Yg + (col + 1) * 100 + row + 8, acc[mt][nt][3]);
            }
        }
    }
}

// ---------------------------------------------------------------------------
// Kernel 3: emb = tanh(Y0 + Â·Y1 + (2Â²−I)·Y2 + cheb_b) + vnr_sum
//   grid 100 (node m), 128 threads. M2 row computed in-block from Â.
// ---------------------------------------------------------------------------
__global__ void emb_kernel(const float* __restrict__ acb,
                           const float* __restrict__ ccb) {
    __shared__ float sA[10000];
    __shared__ float Ar[N_NODES], M2r[N_NODES];
    const int m = blockIdx.x, t = threadIdx.x;
    for (int i = t; i < 10000; i += 128) sA[i] = g_A[i];
    __syncthreads();
    if (t < N_NODES) {
        Ar[t] = sA[m * 100 + t];
        float acc = 0.f;
        #pragma unroll 4
        for (int k = 0; k < N_NODES; k++)
            acc = fmaf(sA[m * 100 + k], sA[k * 100 + t], acc);
        M2r[t] = 2.f * acc - (t == m ? 1.f : 0.f);
    }
    __syncthreads();
    if (t >= 120) return;
    const int h = t / OUT_C, c = t - OUT_C * h;
    const float* y1 = g_Yt + (h * 180 + 60 + c) * 100;
    const float* y2 = g_Yt + (h * 180 + 120 + c) * 100;
    float acc = 0.f;
    #pragma unroll 4
    for (int s = 0; s < N_NODES; s++)
        acc += Ar[s] * y1[s] + M2r[s] * y2[s];
    float pre = g_Yt[(h * 180 + c) * 100 + m] + acc + (h ? ccb[c] : acb[c]);
    g_emb[h * 6000 + m * OUT_C + c] = tanhf(pre) + g_V[h * OUT_C + c];
}

// ---------------------------------------------------------------------------
// Kernel 4: heads. 24 blocks x 128 threads, 250 rows each of the 6000-dot
// ---------------------------------------------------------------------------
__global__ void fc_kernel(const float* __restrict__ afw,
                          const float* __restrict__ cfw,
                          float* __restrict__ out, int out_size) {
    __shared__ float ea[250], ec[250];
    __shared__ float red[4];
    const int b = blockIdx.x, t = threadIdx.x;
    const int i0 = b * 250;

    for (int i = t; i < 250; i += 128) {
        ea[i] = g_emb[i0 + i];
        ec[i] = g_emb[6000 + i0 + i];
    }
    __syncthreads();

    if (t < 100) {
        float acc = 0.f;
        #pragma unroll 5
        for (int i = 0; i < 250; i++)
            acc = fmaf(ea[i], afw[(size_t)(i0 + i) * 100 + t], acc);
        atomicAdd(&out[t], acc);
    }

    float cacc = 0.f;
    for (int i = t; i < 250; i += 128) cacc = fmaf(ec[i], cfw[i0 + i], cacc);
    #pragma unroll
    for (int off = 16; off > 0; off >>= 1)
        cacc += __shfl_down_sync(0xffffffffu, cacc, off);
    if ((t & 31) == 0) red[t >> 5] = cacc;
    __syncthreads();
    if (t == 0 && out_size > 100)
        atomicAdd(&out[100], red[0] + red[1] + red[2] + red[3]);
}

// ---------------------------------------------------------------------------
// Launch
// ---------------------------------------------------------------------------
extern "C" void kernel_launch(void* const* d_in, const int* in_sizes, int n_in,
                              void* d_out, int out_size) {
    const float* x   = (const float*)d_in[0];
    const int*   ei  = (const int*)  d_in[1];
    const float* vnr = (const float*)d_in[2];
    const float* aw  = (const float*)d_in[3];
    const float* acb = (const float*)d_in[4];
    const float* cw  = (const float*)d_in[5];
    const float* ccb = (const float*)d_in[6];
    const float* avw = (const float*)d_in[7];
    const float* avb = (const float*)d_in[8];
    const float* cvw = (const float*)d_in[9];
    const float* cvb = (const float*)d_in[10];
    const float* afw = (const float*)d_in[11];
    const float* afb = (const float*)d_in[12];
    const float* cfw = (const float*)d_in[13];
    const float* cfb = (const float*)d_in[14];
    float* out = (float*)d_out;

    static int smem_set = 0;
    if (!smem_set) {
        cudaFuncSetAttribute(gemm_mma, cudaFuncAttributeMaxDynamicSharedMemorySize, SMEM_B);
        smem_set = 1;
    }

    prep_kernel<<<1, 1024>>>(ei, vnr, avw, avb, cvw, cvb, afb, cfb, out, out_size);
    gemm_mma<<<dim3(NSPLIT, 6), GTHREADS, SMEM_B>>>(x, aw, cw);
    emb_kernel<<<N_NODES, 128>>>(acb, ccb);
    fc_kernel<<<24, 128>>>(afw, cfw, out, out_size);
}

// round 5
// speedup vs baseline: 3.0545x; 1.3290x over previous
#include <cuda_runtime.h>
#include <cuda_bf16.h>
#include <cstdint>
#include <cstddef>

// ---------------------------------------------------------------------------
// Problem constants
// ---------------------------------------------------------------------------
#define N_NODES 100
#define IN_C    65536
#define OUT_C   60
#define N_EDGES 1600
#define NSPLIT  24
#define KTILE   64
#define GTHREADS 256

typedef unsigned int u32;

// ---------------------------------------------------------------------------
// smem word-layout (per stage, 32-bit words)
//   A tiles: 128 rows x 72 bf16 (36 words/row) = 4608 words
//   B tiles:  64 rows x 72 bf16               = 2304 words
// ---------------------------------------------------------------------------
#define AROW_W  36
#define AHI_W   0
#define ALO_W   4608
#define BHI_W   9216
#define BLO_W   11520
#define STAGE_W 13824
#define SMEM_W  (2 * STAGE_W)
#define SMEM_B  (SMEM_W * 4)

__device__ __forceinline__ u32 bfpack2(float lo, float hi) {
    __nv_bfloat162 p = __floats2bfloat162_rn(lo, hi);
    return *(u32*)&p;
}
__device__ __forceinline__ u32 smem_addr_u32(const void* p) {
    u32 a;
    asm("{ .reg .u64 t; cvta.to.shared.u64 t, %1; cvt.u32.u64 %0, t; }"
        : "=r"(a) : "l"(p));
    return a;
}

// mma.sync m16n8k16 row.col f32.bf16.bf16.f32
__device__ __forceinline__ void mma16816(float* c, const u32* a, const u32* b) {
    asm volatile(
        "mma.sync.aligned.m16n8k16.row.col.f32.bf16.bf16.f32 "
        "{%0,%1,%2,%3}, {%4,%5,%6,%7}, {%8,%9}, {%0,%1,%2,%3};"
        : "+f"(c[0]), "+f"(c[1]), "+f"(c[2]), "+f"(c[3])
        : "r"(a[0]), "r"(a[1]), "r"(a[2]), "r"(a[3]), "r"(b[0]), "r"(b[1]));
}

#define LDSM4(r, addr) \
    asm volatile("ldmatrix.sync.aligned.m8n8.x4.shared.b16 {%0,%1,%2,%3}, [%4];" \
        : "=r"((r)[0]), "=r"((r)[1]), "=r"((r)[2]), "=r"((r)[3]) : "r"(addr))

// ---------------------------------------------------------------------------
// Scratch
// ---------------------------------------------------------------------------
__device__ u32   g_Xh[IN_C * N_NODES / 2];   // x hi, bf16 pairs (13.1 MB)
__device__ u32   g_Xl[IN_C * N_NODES / 2];   // x lo residual
__device__ float g_Yt[360 * 100];            // transposed Y: [col][node]
__device__ float g_A[10000];                 // normalized adjacency (Â)
__device__ float g_emb[2 * 6000];
__device__ float g_V[120];

// ---------------------------------------------------------------------------
// Kernel 0: split X into bf16 hi/lo
// ---------------------------------------------------------------------------
__global__ void xsplit_kernel(const float* __restrict__ x) {
    int idx = blockIdx.x * 256 + threadIdx.x;       // 1,638,400 total (x4 floats)
    float4 v = ((const float4*)x)[idx];
    u32 h01 = bfpack2(v.x, v.y), h23 = bfpack2(v.z, v.w);
    float f0 = __uint_as_float(h01 << 16);
    float f1 = __uint_as_float(h01 & 0xffff0000u);
    float f2 = __uint_as_float(h23 << 16);
    float f3 = __uint_as_float(h23 & 0xffff0000u);
    u32 l01 = bfpack2(v.x - f0, v.y - f1);
    u32 l23 = bfpack2(v.z - f2, v.w - f3);
    ((uint2*)g_Xh)[idx] = make_uint2(h01, h23);
    ((uint2*)g_Xl)[idx] = make_uint2(l01, l23);
}

// ---------------------------------------------------------------------------
// Kernel 1: prep — Â, vnr sums, zero Yt, init out with biases
// ---------------------------------------------------------------------------
__global__ void prep_kernel(const int* __restrict__ ei,
                            const float* __restrict__ vnr,
                            const float* __restrict__ avw, const float* __restrict__ avb,
                            const float* __restrict__ cvw, const float* __restrict__ cvb,
                            const float* __restrict__ afb, const float* __restrict__ cfb,
                            float* __restrict__ out, int out_size) {
    __shared__ float sA[10000];
    __shared__ float sdeg[N_NODES];
    const int t = threadIdx.x;  // 1024

    for (int i = t; i < 360 * 100; i += 1024) g_Yt[i] = 0.f;
    for (int i = t; i < 10000; i += 1024) sA[i] = 0.f;
    if (t < N_NODES) sdeg[t] = 0.f;
    __syncthreads();

    for (int e = t; e < N_EDGES; e += 1024) atomicAdd(&sdeg[ei[e]], 1.f);
    __syncthreads();
    if (t < N_NODES) {
        float d = sdeg[t];
        sdeg[t] = (d > 0.f) ? rsqrtf(fmaxf(d, 1.f)) : 0.f;
    }
    __syncthreads();
    for (int e = t; e < N_EDGES; e += 1024) {
        int s = ei[e];
        int d = ei[N_EDGES + e];
        atomicAdd(&sA[d * N_NODES + s], -sdeg[s] * sdeg[d]);
    }
    __syncthreads();
    for (int i = t; i < 10000; i += 1024) g_A[i] = sA[i];

    if (t < OUT_C) {
        float va = 0.f, vc = 0.f;
        #pragma unroll
        for (int i = 0; i < 3; i++) {
            float v = vnr[i];
            va += v * avw[i * OUT_C + t] + avb[i * OUT_C + t];
            vc += v * cvw[i * OUT_C + t] + cvb[i * OUT_C + t];
        }
        g_V[t] = va;
        g_V[OUT_C + t] = vc;
    }

    for (int j = t; j < out_size; j += 1024)
        out[j] = (j < 100) ? afb[j] : ((j == 100) ? cfb[0] : 0.f);
}

// ---------------------------------------------------------------------------
// Kernel 2: bf16-split tensor-core GEMM, ldmatrix + single-sync pipeline
// ---------------------------------------------------------------------------
__global__ __launch_bounds__(GTHREADS, 1)
void gemm_mma(const float* __restrict__ aw,
              const float* __restrict__ cw) {
    extern __shared__ u32 smw[];
    const int t = threadIdx.x;
    const int lane = t & 31, wid = t >> 5;
    const int wm = wid >> 1, wn = wid & 1;
    const int hk = blockIdx.y;
    const float* Wbase = ((hk >= 3) ? cw : aw) + (size_t)(hk % 3) * IN_C * OUT_C;

    int k0 = (int)(((long long)blockIdx.x * IN_C) / NSPLIT) & ~(KTILE - 1);
    int k1 = (int)(((long long)(blockIdx.x + 1) * IN_C) / NSPLIT) & ~(KTILE - 1);
    const int nch = (k1 - k0) / KTILE;

    for (int i = t; i < SMEM_W; i += GTHREADS) smw[i] = 0;

    float acc[2][4][4];
    #pragma unroll
    for (int mt = 0; mt < 2; mt++)
        #pragma unroll
        for (int nt = 0; nt < 4; nt++)
            #pragma unroll
            for (int q = 0; q < 4; q++) acc[mt][nt][q] = 0.f;

    // ---- fragment smem addresses (bytes), stage-relative
    const u32 sbase = smem_addr_u32(smw);
    const int t2 = lane >> 3, rr = lane & 7;
    const u32 a_off = (u32)((wm * 32 + rr + (t2 & 1) * 8) * AROW_W + (t2 >> 1) * 4) * 4;
    const u32 b_off = (u32)(BHI_W * 4) +
                      (u32)((wn * 32 + rr + (t2 >> 1) * 8) * AROW_W + (t2 & 1) * 4) * 4;

    uint2 xh[7], xl[7];
    float wr[15];

    // ---- preamble: load + store stage 0
    {
        int kb = k0;
        #pragma unroll
        for (int i = 0; i < 7; i++) {
            int idx = t + i * GTHREADS;
            if (idx < 1600) {
                int m = idx >> 4, q = idx & 15;
                size_t w = ((size_t)m * IN_C + kb) / 2 + q * 2;
                xh[i] = *(const uint2*)(g_Xh + w);
                xl[i] = *(const uint2*)(g_Xl + w);
            }
        }
        #pragma unroll
        for (int i = 0; i < 15; i++) {
            int idx = t + i * GTHREADS;
            int k = idx / OUT_C, ch = idx - k * OUT_C;
            wr[i] = Wbase[(size_t)(kb + k) * OUT_C + ch];
        }
    }
    __syncthreads();   // zeroing done
    {
        u32* sb = smw;
        #pragma unroll
        for (int i = 0; i < 7; i++) {
            int idx = t + i * GTHREADS;
            if (idx < 1600) {
                int m = idx >> 4, q = idx & 15;
                int wofs = m * AROW_W + q * 2;
                *(uint2*)(sb + AHI_W + wofs) = xh[i];
                *(uint2*)(sb + ALO_W + wofs) = xl[i];
            }
        }
        #pragma unroll
        for (int i = 0; i < 15; i++) {
            int idx = t + i * GTHREADS;
            int k = idx / OUT_C, ch = idx - k * OUT_C;
            float w = wr[i];
            __nv_bfloat16 wh = __float2bfloat16(w);
            float whf = __uint_as_float(((u32)*(unsigned short*)&wh) << 16);
            __nv_bfloat16 wl = __float2bfloat16(w - whf);
            ((__nv_bfloat16*)(sb + BHI_W))[ch * 72 + k] = wh;
            ((__nv_bfloat16*)(sb + BLO_W))[ch * 72 + k] = wl;
        }
    }
    __syncthreads();

    for (int c = 0; c < nch; c++) {
        const u32 stb = sbase + ((c & 1) ? STAGE_W * 4 : 0);
        const bool more = (c + 1 < nch);

        // ---- issue gmem prefetch for stage c+1
        if (more) {
            int kb = k0 + (c + 1) * KTILE;
            #pragma unroll
            for (int i = 0; i < 7; i++) {
                int idx = t + i * GTHREADS;
                if (idx < 1600) {
                    int m = idx >> 4, q = idx & 15;
                    size_t w = ((size_t)m * IN_C + kb) / 2 + q * 2;
                    xh[i] = *(const uint2*)(g_Xh + w);
                    xl[i] = *(const uint2*)(g_Xl + w);
                }
            }
            #pragma unroll
            for (int i = 0; i < 15; i++) {
                int idx = t + i * GTHREADS;
                int k = idx / OUT_C, ch = idx - k * OUT_C;
                wr[i] = Wbase[(size_t)(kb + k) * OUT_C + ch];
            }
        }

        // ---- HMMA on stage c (ldmatrix fragments)
        #pragma unroll
        for (int kc = 0; kc < 4; kc++) {
            const u32 ko = kc * 32;
            u32 ah0[4], ah1[4], al0[4], al1[4];
            u32 b0[4], b1[4], c0[4], c1[4];
            LDSM4(ah0, stb + a_off + ko);
            LDSM4(ah1, stb + a_off + 2304 + ko);
            LDSM4(al0, stb + a_off + 18432 + ko);
            LDSM4(al1, stb + a_off + 18432 + 2304 + ko);
            LDSM4(b0, stb + b_off + ko);
            LDSM4(b1, stb + b_off + 2304 + ko);
            LDSM4(c0, stb + b_off + 9216 + ko);
            LDSM4(c1, stb + b_off + 9216 + 2304 + ko);

            const u32* bh[4] = { b0, b0 + 2, b1, b1 + 2 };
            const u32* bl[4] = { c0, c0 + 2, c1, c1 + 2 };
            #pragma unroll
            for (int nt = 0; nt < 4; nt++) {
                mma16816(acc[0][nt], ah0, bh[nt]);
                mma16816(acc[1][nt], ah1, bh[nt]);
                mma16816(acc[0][nt], ah0, bl[nt]);
                mma16816(acc[1][nt], ah1, bl[nt]);
                mma16816(acc[0][nt], al0, bh[nt]);
                mma16816(acc[1][nt], al1, bh[nt]);
            }
        }

        // ---- convert+store stage c+1 into the other buffer
        if (more) {
            u32* sb = smw + ((c + 1) & 1) * STAGE_W;
            #pragma unroll
            for (int i = 0; i < 7; i++) {
                int idx = t + i * GTHREADS;
                if (idx < 1600) {
                    int m = idx >> 4, q = idx & 15;
                    int wofs = m * AROW_W + q * 2;
                    *(uint2*)(sb + AHI_W + wofs) = xh[i];
                    *(uint2*)(sb + ALO_W + wofs) = xl[i];
                }
            }
            #pragma unroll
            for (int i = 0; i < 15; i++) {
                int idx = t + i * GTHREADS;
                int k = idx / OUT_C, ch = idx - k * OUT_C;
                float w = wr[i];
                __nv_bfloat16 wh = __float2bfloat16(w);
                float whf = __uint_as_float(((u32)*(unsigned short*)&wh) << 16);
                __nv_bfloat16 wl = __float2bfloat16(w - whf);
                ((__nv_bfloat16*)(sb + BHI_W))[ch * 72 + k] = wh;
                ((__nv_bfloat16*)(sb + BLO_W))[ch * 72 + k] = wl;
            }
        }
        __syncthreads();
    }

    // ---- epilogue: atomicAdd into transposed Yt
    const int r = lane >> 2, cb = (lane & 3) * 2;
    float* Yg = g_Yt + hk * 60 * 100;
    #pragma unroll
    for (int mt = 0; mt < 2; mt++) {
        int row = wm * 32 + mt * 16 + r;
        #pragma unroll
        for (int nt = 0; nt < 4; nt++) {
            int col = wn * 32 + nt * 8 + cb;
            if (col < OUT_C) {
                if (row < N_NODES)     atomicAdd(Yg + col * 100 + row,     acc[mt][nt][0]);
                if (row + 8 < N_NODES) atomicAdd(Yg + col * 100 + row + 8, acc[mt][nt][2]);
            }
            if (col + 1 < OUT_C) {
                if (row < N_NODES)     atomicAdd(Yg + (col + 1) * 100 + row,     acc[mt][nt][1]);
                if (row + 8 < N_NODES) atomicAdd(Yg + (col + 1) * 100 + row + 8, acc[mt][nt][3]);
            }
        }
    }
}

// ---------------------------------------------------------------------------
// Kernel 3: emb columns. grid 120 = (h, c); 128 threads.
//   emb[:,h,c] = tanh(y0 + Â(y1 + 2v) − y2 + b), v = Â y2   (all coalesced)
// ---------------------------------------------------------------------------
__global__ void emb2_kernel(const float* __restrict__ acb,
                            const float* __restrict__ ccb) {
    __shared__ float sA[100 * 101];
    __shared__ float y0[100], y1[100], y2[100], vv[100];
    const int b = blockIdx.x, t = threadIdx.x;
    const int h = b / OUT_C, c = b - OUT_C * h;

    for (int i = t; i < 10000; i += 128) {
        int row = i / 100, col = i - 100 * row;
        sA[row * 101 + col] = g_A[i];
    }
    if (t < N_NODES) {
        y0[t] = g_Yt[(h * 180 + c) * 100 + t];
        y1[t] = g_Yt[(h * 180 + 60 + c) * 100 + t];
        y2[t] = g_Yt[(h * 180 + 120 + c) * 100 + t];
    }
    __syncthreads();

    if (t < N_NODES) {
        const float* Ar = sA + t * 101;
        float a0 = 0.f, a1 = 0.f;
        #pragma unroll 10
        for (int k = 0; k < N_NODES; k += 2) {
            a0 = fmaf(Ar[k], y2[k], a0);
            a1 = fmaf(Ar[k + 1], y2[k + 1], a1);
        }
        vv[t] = a0 + a1;
    }
    __syncthreads();

    if (t < N_NODES) {
        const float* Ar = sA + t * 101;
        float a0 = 0.f, a1 = 0.f;
        #pragma unroll 10
        for (int k = 0; k < N_NODES; k += 2) {
            a0 = fmaf(Ar[k], fmaf(2.f, vv[k], y1[k]), a0);
            a1 = fmaf(Ar[k + 1], fmaf(2.f, vv[k + 1], y1[k + 1]), a1);
        }
        float pre = y0[t] + a0 + a1 - y2[t] + (h ? ccb[c] : acb[c]);
        g_emb[h * 6000 + t * OUT_C + c] = tanhf(pre) + g_V[h * OUT_C + c];
    }
}

// ---------------------------------------------------------------------------
// Kernel 4: heads. 120 blocks x 128 threads, 50 rows each of the 6000-dot
// ---------------------------------------------------------------------------
__global__ void fc_kernel(const float* __restrict__ afw,
                          const float* __restrict__ cfw,
                          float* __restrict__ out, int out_size) {
    __shared__ float ea[50], ec[50];
    __shared__ float red[4];
    const int b = blockIdx.x, t = threadIdx.x;
    const int i0 = b * 50;

    if (t < 50) {
        ea[t] = g_emb[i0 + t];
        ec[t] = g_emb[6000 + i0 + t];
    }
    __syncthreads();

    if (t < 100) {
        float a0 = 0.f, a1 = 0.f;
        #pragma unroll 5
        for (int i = 0; i < 50; i += 2) {
            a0 = fmaf(ea[i],     afw[(size_t)(i0 + i) * 100 + t],     a0);
            a1 = fmaf(ea[i + 1], afw[(size_t)(i0 + i + 1) * 100 + t], a1);
        }
        atomicAdd(&out[t], a0 + a1);
    }

    float v = (t < 50) ? ec[t] * cfw[i0 + t] : 0.f;
    #pragma unroll
    for (int off = 16; off > 0; off >>= 1)
        v += __shfl_down_sync(0xffffffffu, v, off);
    if ((t & 31) == 0) red[t >> 5] = v;
    __syncthreads();
    if (t == 0 && out_size > 100)
        atomicAdd(&out[100], red[0] + red[1] + red[2] + red[3]);
}

// ---------------------------------------------------------------------------
// Launch
// ---------------------------------------------------------------------------
extern "C" void kernel_launch(void* const* d_in, const int* in_sizes, int n_in,
                              void* d_out, int out_size) {
    const float* x   = (const float*)d_in[0];
    const int*   ei  = (const int*)  d_in[1];
    const float* vnr = (const float*)d_in[2];
    const float* aw  = (const float*)d_in[3];
    const float* acb = (const float*)d_in[4];
    const float* cw  = (const float*)d_in[5];
    const float* ccb = (const float*)d_in[6];
    const float* avw = (const float*)d_in[7];
    const float* avb = (const float*)d_in[8];
    const float* cvw = (const float*)d_in[9];
    const float* cvb = (const float*)d_in[10];
    const float* afw = (const float*)d_in[11];
    const float* afb = (const float*)d_in[12];
    const float* cfw = (const float*)d_in[13];
    const float* cfb = (const float*)d_in[14];
    float* out = (float*)d_out;

    static int smem_set = 0;
    if (!smem_set) {
        cudaFuncSetAttribute(gemm_mma, cudaFuncAttributeMaxDynamicSharedMemorySize, SMEM_B);
        smem_set = 1;
    }

    xsplit_kernel<<<6400, 256>>>(x);
    prep_kernel<<<1, 1024>>>(ei, vnr, avw, avb, cvw, cvb, afb, cfb, out, out_size);
    gemm_mma<<<dim3(NSPLIT, 6), GTHREADS, SMEM_B>>>(aw, cw);
    emb2_kernel<<<120, 128>>>(acb, ccb);
    fc_kernel<<<120, 128>>>(afw, cfw, out, out_size);
}

// round 6
// speedup vs baseline: 3.1118x; 1.0188x over previous
#include <cuda_runtime.h>
#include <cuda_bf16.h>
#include <cstdint>
#include <cstddef>

// ---------------------------------------------------------------------------
// Problem constants
// ---------------------------------------------------------------------------
#define N_NODES 100
#define IN_C    65536
#define OUT_C   60
#define N_EDGES 1600
#define NSPLIT  48
#define KTILE   32
#define GTHREADS 256

typedef unsigned int u32;

// ---------------------------------------------------------------------------
// smem word-layout (per stage, 32-bit words). Rows padded to 20 words (80 B)
// so every 16B ldmatrix row stays 16B-aligned and banks are conflict-free.
//   A tiles: 128 rows x 20 words = 2560 words each (hi, lo)
//   B tiles:  64 rows x 20 words = 1280 words each (hi, lo)
// ---------------------------------------------------------------------------
#define AROW_W  20
#define AHI_W   0
#define ALO_W   2560
#define BHI_W   5120
#define BLO_W   6400
#define STAGE_W 7680
#define SMEM_W  (2 * STAGE_W)
#define SMEM_B  (SMEM_W * 4)        // 61440 bytes -> 2 blocks/SM

__device__ __forceinline__ u32 bfpack2(float lo, float hi) {
    __nv_bfloat162 p = __floats2bfloat162_rn(lo, hi);
    return *(u32*)&p;
}
__device__ __forceinline__ u32 smem_addr_u32(const void* p) {
    u32 a;
    asm("{ .reg .u64 t; cvta.to.shared.u64 t, %1; cvt.u32.u64 %0, t; }"
        : "=r"(a) : "l"(p));
    return a;
}

// mma.sync m16n8k16 row.col f32.bf16.bf16.f32
__device__ __forceinline__ void mma16816(float* c, const u32* a, const u32* b) {
    asm volatile(
        "mma.sync.aligned.m16n8k16.row.col.f32.bf16.bf16.f32 "
        "{%0,%1,%2,%3}, {%4,%5,%6,%7}, {%8,%9}, {%0,%1,%2,%3};"
        : "+f"(c[0]), "+f"(c[1]), "+f"(c[2]), "+f"(c[3])
        : "r"(a[0]), "r"(a[1]), "r"(a[2]), "r"(a[3]), "r"(b[0]), "r"(b[1]));
}

#define LDSM4(r, addr) \
    asm volatile("ldmatrix.sync.aligned.m8n8.x4.shared.b16 {%0,%1,%2,%3}, [%4];" \
        : "=r"((r)[0]), "=r"((r)[1]), "=r"((r)[2]), "=r"((r)[3]) : "r"(addr))

// ---------------------------------------------------------------------------
// Scratch
// ---------------------------------------------------------------------------
__device__ u32   g_Xh[IN_C * N_NODES / 2];   // x hi, bf16 pairs (13.1 MB)
__device__ u32   g_Xl[IN_C * N_NODES / 2];   // x lo residual
__device__ float g_Yt[360 * 100];            // transposed Y: [col][node]
__device__ float g_A[10000];                 // normalized adjacency (Â)
__device__ float g_emb[2 * 6000];
__device__ float g_V[120];

// ---------------------------------------------------------------------------
// Kernel 0: split X into bf16 hi/lo; first 36 blocks also zero Yt
// ---------------------------------------------------------------------------
__global__ void xsplit_kernel(const float* __restrict__ x) {
    int idx = blockIdx.x * 256 + threadIdx.x;       // 1,638,400 float4
    if (blockIdx.x < 36) {
        int z = blockIdx.x * 256 + threadIdx.x;
        if (z < 9000) ((float4*)g_Yt)[z] = make_float4(0.f, 0.f, 0.f, 0.f);
    }
    float4 v = ((const float4*)x)[idx];
    u32 h01 = bfpack2(v.x, v.y), h23 = bfpack2(v.z, v.w);
    float f0 = __uint_as_float(h01 << 16);
    float f1 = __uint_as_float(h01 & 0xffff0000u);
    float f2 = __uint_as_float(h23 << 16);
    float f3 = __uint_as_float(h23 & 0xffff0000u);
    u32 l01 = bfpack2(v.x - f0, v.y - f1);
    u32 l23 = bfpack2(v.z - f2, v.w - f3);
    ((uint2*)g_Xh)[idx] = make_uint2(h01, h23);
    ((uint2*)g_Xl)[idx] = make_uint2(l01, l23);
}

// ---------------------------------------------------------------------------
// Kernel 1: prep — Â, vnr sums, init out with biases
// ---------------------------------------------------------------------------
__global__ void prep_kernel(const int* __restrict__ ei,
                            const float* __restrict__ vnr,
                            const float* __restrict__ avw, const float* __restrict__ avb,
                            const float* __restrict__ cvw, const float* __restrict__ cvb,
                            const float* __restrict__ afb, const float* __restrict__ cfb,
                            float* __restrict__ out, int out_size) {
    __shared__ float sA[10000];
    __shared__ float sdeg[N_NODES];
    const int t = threadIdx.x;  // 1024

    for (int i = t; i < 10000; i += 1024) sA[i] = 0.f;
    if (t < N_NODES) sdeg[t] = 0.f;
    __syncthreads();

    for (int e = t; e < N_EDGES; e += 1024) atomicAdd(&sdeg[ei[e]], 1.f);
    __syncthreads();
    if (t < N_NODES) {
        float d = sdeg[t];
        sdeg[t] = (d > 0.f) ? rsqrtf(fmaxf(d, 1.f)) : 0.f;
    }
    __syncthreads();
    for (int e = t; e < N_EDGES; e += 1024) {
        int s = ei[e];
        int d = ei[N_EDGES + e];
        atomicAdd(&sA[d * N_NODES + s], -sdeg[s] * sdeg[d]);
    }
    __syncthreads();
    for (int i = t; i < 10000; i += 1024) g_A[i] = sA[i];

    if (t < OUT_C) {
        float va = 0.f, vc = 0.f;
        #pragma unroll
        for (int i = 0; i < 3; i++) {
            float v = vnr[i];
            va += v * avw[i * OUT_C + t] + avb[i * OUT_C + t];
            vc += v * cvw[i * OUT_C + t] + cvb[i * OUT_C + t];
        }
        g_V[t] = va;
        g_V[OUT_C + t] = vc;
    }

    for (int j = t; j < out_size; j += 1024)
        out[j] = (j < 100) ? afb[j] : ((j == 100) ? cfb[0] : 0.f);
}

// ---------------------------------------------------------------------------
// Kernel 2: bf16-split tensor-core GEMM, occupancy 2, padded-M tile skipped
// ---------------------------------------------------------------------------
__global__ __launch_bounds__(GTHREADS, 2)
void gemm_mma(const float* __restrict__ aw,
              const float* __restrict__ cw) {
    extern __shared__ u32 smw[];
    const int t = threadIdx.x;
    const int lane = t & 31, wid = t >> 5;
    const int wm = wid >> 1, wn = wid & 1;
    const bool do_mt1 = (wm < 3);          // wm==3, mt==1 covers rows 112-127: all pad
    const int hk = blockIdx.y;
    const float* Wbase = ((hk >= 3) ? cw : aw) + (size_t)(hk % 3) * IN_C * OUT_C;

    int k0 = (int)(((long long)blockIdx.x * IN_C) / NSPLIT) & ~(KTILE - 1);
    int k1 = (int)(((long long)(blockIdx.x + 1) * IN_C) / NSPLIT) & ~(KTILE - 1);
    const int nch = (k1 - k0) / KTILE;

    for (int i = t; i < SMEM_W; i += GTHREADS) smw[i] = 0;

    float acc[2][4][4];
    #pragma unroll
    for (int mt = 0; mt < 2; mt++)
        #pragma unroll
        for (int nt = 0; nt < 4; nt++)
            #pragma unroll
            for (int q = 0; q < 4; q++) acc[mt][nt][q] = 0.f;

    // fragment smem byte addresses (stage-relative)
    const u32 sbase = smem_addr_u32(smw);
    const int t2 = lane >> 3, rr = lane & 7;
    const u32 a_off = (u32)(((wm * 32 + rr + (t2 & 1) * 8) * AROW_W + (t2 >> 1) * 4) * 4);
    const u32 b_off = (u32)(BHI_W * 4) +
                      (u32)(((wn * 32 + rr + (t2 >> 1) * 8) * AROW_W + (t2 & 1) * 4) * 4);

    uint2 xh[4], xl[4];
    float wr[8];

    // ---- preamble: load stage 0
    {
        int kb = k0;
        #pragma unroll
        for (int i = 0; i < 4; i++) {
            int idx = t + i * GTHREADS;       // < 1024
            int m = idx >> 3, q = idx & 7;
            if (m < N_NODES) {
                size_t w = (size_t)m * (IN_C / 2) + (kb >> 1) + q * 2;
                xh[i] = *(const uint2*)(g_Xh + w);
                xl[i] = *(const uint2*)(g_Xl + w);
            }
        }
        #pragma unroll
        for (int i = 0; i < 8; i++) {
            int idx = t + i * GTHREADS;
            if (idx < KTILE * OUT_C) {
                int k = idx / OUT_C, ch = idx - k * OUT_C;
                wr[i] = Wbase[(size_t)(kb + k) * OUT_C + ch];
            }
        }
    }
    __syncthreads();   // zeroing done
    {
        u32* sb = smw;
        #pragma unroll
        for (int i = 0; i < 4; i++) {
            int idx = t + i * GTHREADS;
            int m = idx >> 3, q = idx & 7;
            if (m < N_NODES) {
                int wofs = m * AROW_W + q * 2;
                *(uint2*)(sb + AHI_W + wofs) = xh[i];
                *(uint2*)(sb + ALO_W + wofs) = xl[i];
            }
        }
        #pragma unroll
        for (int i = 0; i < 8; i++) {
            int idx = t + i * GTHREADS;
            if (idx < KTILE * OUT_C) {
                int k = idx / OUT_C, ch = idx - k * OUT_C;
                float w = wr[i];
                __nv_bfloat16 wh = __float2bfloat16(w);
                float whf = __uint_as_float(((u32)*(unsigned short*)&wh) << 16);
                __nv_bfloat16 wl = __float2bfloat16(w - whf);
                ((__nv_bfloat16*)(sb + BHI_W))[ch * 2 * AROW_W + k] = wh;
                ((__nv_bfloat16*)(sb + BLO_W))[ch * 2 * AROW_W + k] = wl;
            }
        }
    }
    __syncthreads();

    for (int c = 0; c < nch; c++) {
        const u32 stb = sbase + ((c & 1) ? STAGE_W * 4 : 0);
        const bool more = (c + 1 < nch);

        // ---- gmem prefetch for stage c+1
        if (more) {
            int kb = k0 + (c + 1) * KTILE;
            #pragma unroll
            for (int i = 0; i < 4; i++) {
                int idx = t + i * GTHREADS;
                int m = idx >> 3, q = idx & 7;
                if (m < N_NODES) {
                    size_t w = (size_t)m * (IN_C / 2) + (kb >> 1) + q * 2;
                    xh[i] = *(const uint2*)(g_Xh + w);
                    xl[i] = *(const uint2*)(g_Xl + w);
                }
            }
            #pragma unroll
            for (int i = 0; i < 8; i++) {
                int idx = t + i * GTHREADS;
                if (idx < KTILE * OUT_C) {
                    int k = idx / OUT_C, ch = idx - k * OUT_C;
                    wr[i] = Wbase[(size_t)(kb + k) * OUT_C + ch];
                }
            }
        }

        // ---- HMMA on stage c
        #pragma unroll
        for (int kc = 0; kc < 2; kc++) {
            const u32 ko = kc * 32;
            u32 ah0[4], ah1[4], al0[4], al1[4];
            u32 b0[4], b1[4], c0[4], c1[4];
            LDSM4(ah0, stb + a_off + ko);
            if (do_mt1) LDSM4(ah1, stb + a_off + 1280 + ko);
            LDSM4(al0, stb + a_off + 10240 + ko);
            if (do_mt1) LDSM4(al1, stb + a_off + 10240 + 1280 + ko);
            LDSM4(b0, stb + b_off + ko);
            LDSM4(b1, stb + b_off + 1280 + ko);
            LDSM4(c0, stb + b_off + 5120 + ko);
            LDSM4(c1, stb + b_off + 5120 + 1280 + ko);

            const u32* bh[4] = { b0, b0 + 2, b1, b1 + 2 };
            const u32* bl[4] = { c0, c0 + 2, c1, c1 + 2 };
            #pragma unroll
            for (int nt = 0; nt < 4; nt++) {
                mma16816(acc[0][nt], ah0, bh[nt]);
                mma16816(acc[0][nt], ah0, bl[nt]);
                mma16816(acc[0][nt], al0, bh[nt]);
                if (do_mt1) {
                    mma16816(acc[1][nt], ah1, bh[nt]);
                    mma16816(acc[1][nt], ah1, bl[nt]);
                    mma16816(acc[1][nt], al1, bh[nt]);
                }
            }
        }

        // ---- convert+store stage c+1
        if (more) {
            u32* sb = smw + ((c + 1) & 1) * STAGE_W;
            #pragma unroll
            for (int i = 0; i < 4; i++) {
                int idx = t + i * GTHREADS;
                int m = idx >> 3, q = idx & 7;
                if (m < N_NODES) {
                    int wofs = m * AROW_W + q * 2;
                    *(uint2*)(sb + AHI_W + wofs) = xh[i];
                    *(uint2*)(sb + ALO_W + wofs) = xl[i];
                }
            }
            #pragma unroll
            for (int i = 0; i < 8; i++) {
                int idx = t + i * GTHREADS;
                if (idx < KTILE * OUT_C) {
                    int k = idx / OUT_C, ch = idx - k * OUT_C;
                    float w = wr[i];
                    __nv_bfloat16 wh = __float2bfloat16(w);
                    float whf = __uint_as_float(((u32)*(unsigned short*)&wh) << 16);
                    __nv_bfloat16 wl = __float2bfloat16(w - whf);
                    ((__nv_bfloat16*)(sb + BHI_W))[ch * 2 * AROW_W + k] = wh;
                    ((__nv_bfloat16*)(sb + BLO_W))[ch * 2 * AROW_W + k] = wl;
                }
            }
        }
        __syncthreads();
    }

    // ---- epilogue: atomicAdd into transposed Yt
    const int r = lane >> 2, cb = (lane & 3) * 2;
    float* Yg = g_Yt + hk * 60 * 100;
    #pragma unroll
    for (int mt = 0; mt < 2; mt++) {
        int row = wm * 32 + mt * 16 + r;
        #pragma unroll
        for (int nt = 0; nt < 4; nt++) {
            int col = wn * 32 + nt * 8 + cb;
            if (col < OUT_C) {
                if (row < N_NODES)     atomicAdd(Yg + col * 100 + row,     acc[mt][nt][0]);
                if (row + 8 < N_NODES) atomicAdd(Yg + col * 100 + row + 8, acc[mt][nt][2]);
            }
            if (col + 1 < OUT_C) {
                if (row < N_NODES)     atomicAdd(Yg + (col + 1) * 100 + row,     acc[mt][nt][1]);
                if (row + 8 < N_NODES) atomicAdd(Yg + (col + 1) * 100 + row + 8, acc[mt][nt][3]);
            }
        }
    }
}

// ---------------------------------------------------------------------------
// Kernel 3: emb columns; Â rows read as float4 straight from L2 (MLP 25)
//   emb[:,h,c] = tanh(y0 + Â(y1 + 2 Â y2) − y2 + b) + vnr
// ---------------------------------------------------------------------------
__global__ void emb3_kernel(const float* __restrict__ acb,
                            const float* __restrict__ ccb) {
    __shared__ float y0[100], y1[100], y2[104], zz[104];
    const int b = blockIdx.x, t = threadIdx.x;
    const int h = b / OUT_C, c = b - OUT_C * h;

    if (t < N_NODES) {
        y0[t] = g_Yt[(h * 180 + c) * 100 + t];
        y1[t] = g_Yt[(h * 180 + 60 + c) * 100 + t];
        y2[t] = g_Yt[(h * 180 + 120 + c) * 100 + t];
    }
    __syncthreads();

    if (t < N_NODES) {
        const float4* Ar = (const float4*)(g_A + t * 100);
        float a0 = 0.f, a1 = 0.f, a2 = 0.f, a3 = 0.f;
        #pragma unroll
        for (int q = 0; q < 25; q++) {
            float4 av = Ar[q];
            a0 = fmaf(av.x, y2[q * 4 + 0], a0);
            a1 = fmaf(av.y, y2[q * 4 + 1], a1);
            a2 = fmaf(av.z, y2[q * 4 + 2], a2);
            a3 = fmaf(av.w, y2[q * 4 + 3], a3);
        }
        zz[t] = fmaf(2.f, (a0 + a1) + (a2 + a3), y1[t]);
    }
    __syncthreads();

    if (t < N_NODES) {
        const float4* Ar = (const float4*)(g_A + t * 100);
        float a0 = 0.f, a1 = 0.f, a2 = 0.f, a3 = 0.f;
        #pragma unroll
        for (int q = 0; q < 25; q++) {
            float4 av = Ar[q];
            a0 = fmaf(av.x, zz[q * 4 + 0], a0);
            a1 = fmaf(av.y, zz[q * 4 + 1], a1);
            a2 = fmaf(av.z, zz[q * 4 + 2], a2);
            a3 = fmaf(av.w, zz[q * 4 + 3], a3);
        }
        float pre = y0[t] + (a0 + a1) + (a2 + a3) - y2[t] + (h ? ccb[c] : acb[c]);
        g_emb[h * 6000 + t * OUT_C + c] = tanhf(pre) + g_V[h * OUT_C + c];
    }
}

// ---------------------------------------------------------------------------
// Kernel 4: heads. 120 blocks x 128 threads, 50 rows each of the 6000-dot
// ---------------------------------------------------------------------------
__global__ void fc_kernel(const float* __restrict__ afw,
                          const float* __restrict__ cfw,
                          float* __restrict__ out, int out_size) {
    __shared__ float ea[50], ec[50];
    __shared__ float red[4];
    const int b = blockIdx.x, t = threadIdx.x;
    const int i0 = b * 50;

    if (t < 50) {
        ea[t] = g_emb[i0 + t];
        ec[t] = g_emb[6000 + i0 + t];
    }
    __syncthreads();

    if (t < 100) {
        float a0 = 0.f, a1 = 0.f;
        #pragma unroll 5
        for (int i = 0; i < 50; i += 2) {
            a0 = fmaf(ea[i],     afw[(size_t)(i0 + i) * 100 + t],     a0);
            a1 = fmaf(ea[i + 1], afw[(size_t)(i0 + i + 1) * 100 + t], a1);
        }
        atomicAdd(&out[t], a0 + a1);
    }

    float v = (t < 50) ? ec[t] * cfw[i0 + t] : 0.f;
    #pragma unroll
    for (int off = 16; off > 0; off >>= 1)
        v += __shfl_down_sync(0xffffffffu, v, off);
    if ((t & 31) == 0) red[t >> 5] = v;
    __syncthreads();
    if (t == 0 && out_size > 100)
        atomicAdd(&out[100], red[0] + red[1] + red[2] + red[3]);
}

// ---------------------------------------------------------------------------
// Launch
// ---------------------------------------------------------------------------
extern "C" void kernel_launch(void* const* d_in, const int* in_sizes, int n_in,
                              void* d_out, int out_size) {
    const float* x   = (const float*)d_in[0];
    const int*   ei  = (const int*)  d_in[1];
    const float* vnr = (const float*)d_in[2];
    const float* aw  = (const float*)d_in[3];
    const float* acb = (const float*)d_in[4];
    const float* cw  = (const float*)d_in[5];
    const float* ccb = (const float*)d_in[6];
    const float* avw = (const float*)d_in[7];
    const float* avb = (const float*)d_in[8];
    const float* cvw = (const float*)d_in[9];
    const float* cvb = (const float*)d_in[10];
    const float* afw = (const float*)d_in[11];
    const float* afb = (const float*)d_in[12];
    const float* cfw = (const float*)d_in[13];
    const float* cfb = (const float*)d_in[14];
    float* out = (float*)d_out;

    static int smem_set = 0;
    if (!smem_set) {
        cudaFuncSetAttribute(gemm_mma, cudaFuncAttributeMaxDynamicSharedMemorySize, SMEM_B);
        smem_set = 1;
    }

    xsplit_kernel<<<6400, 256>>>(x);
    prep_kernel<<<1, 1024>>>(ei, vnr, avw, avb, cvw, cvb, afb, cfb, out, out_size);
    gemm_mma<<<dim3(NSPLIT, 6), GTHREADS, SMEM_B>>>(aw, cw);
    emb3_kernel<<<120, 128>>>(acb, ccb);
    fc_kernel<<<120, 128>>>(afw, cfw, out, out_size);
}

// round 7
// speedup vs baseline: 3.7676x; 1.2107x over previous
#include <cuda_runtime.h>
#include <cuda_fp16.h>
#include <cuda_bf16.h>
#include <cstdint>
#include <cstddef>

// ---------------------------------------------------------------------------
// Problem constants
// ---------------------------------------------------------------------------
#define N_NODES 100
#define IN_C    65536
#define OUT_C   60
#define N_EDGES 1600
#define NSPLIT  48
#define KTILE   64
#define GTHREADS 256

typedef unsigned int u32;

// ---------------------------------------------------------------------------
// smem word-layout (per stage, 32-bit words). Rows padded to 72 fp16
// (36 words, 144 B) so ldmatrix rows are 16B-aligned and conflict-free.
//   A tiles: 128 rows x 36 words = 4608 words each (hi, lo)
//   B tile :  64 rows x 36 words = 2304 words (hi only — fp16 2-term split)
// ---------------------------------------------------------------------------
#define AROW_W  36
#define AHI_W   0
#define ALO_W   4608
#define BHI_W   9216
#define STAGE_W 11520
#define SMEM_W  (2 * STAGE_W)
#define SMEM_B  (SMEM_W * 4)        // 92160 bytes -> 2 blocks/SM

__device__ __forceinline__ u32 smem_addr_u32(const void* p) {
    u32 a;
    asm("{ .reg .u64 t; cvta.to.shared.u64 t, %1; cvt.u32.u64 %0, t; }"
        : "=r"(a) : "l"(p));
    return a;
}

// mma.sync m16n8k16 row.col f32.f16.f16.f32
__device__ __forceinline__ void mma16816(float* c, const u32* a, const u32* b) {
    asm volatile(
        "mma.sync.aligned.m16n8k16.row.col.f32.f16.f16.f32 "
        "{%0,%1,%2,%3}, {%4,%5,%6,%7}, {%8,%9}, {%0,%1,%2,%3};"
        : "+f"(c[0]), "+f"(c[1]), "+f"(c[2]), "+f"(c[3])
        : "r"(a[0]), "r"(a[1]), "r"(a[2]), "r"(a[3]), "r"(b[0]), "r"(b[1]));
}

#define LDSM4(r, addr) \
    asm volatile("ldmatrix.sync.aligned.m8n8.x4.shared.b16 {%0,%1,%2,%3}, [%4];" \
        : "=r"((r)[0]), "=r"((r)[1]), "=r"((r)[2]), "=r"((r)[3]) : "r"(addr))

// ---------------------------------------------------------------------------
// Scratch
// ---------------------------------------------------------------------------
__device__ u32   g_Xh[IN_C * N_NODES / 2];   // x hi, fp16 pairs (13.1 MB)
__device__ u32   g_Xl[IN_C * N_NODES / 2];   // x lo residual, fp16 pairs
__device__ float g_Yt[360 * 100];            // transposed Y: [col][node]
__device__ float g_A[10000];                 // normalized adjacency (Â)
__device__ float g_emb[2 * 6000];
__device__ float g_V[120];

// ---------------------------------------------------------------------------
// Kernel 0: split X into fp16 hi/lo; first 36 blocks also zero Yt
// ---------------------------------------------------------------------------
__global__ void xsplit_kernel(const float* __restrict__ x) {
    int idx = blockIdx.x * 256 + threadIdx.x;       // 1,638,400 float4
    if (blockIdx.x < 36) {
        int z = blockIdx.x * 256 + threadIdx.x;
        if (z < 9000) ((float4*)g_Yt)[z] = make_float4(0.f, 0.f, 0.f, 0.f);
    }
    float4 v = ((const float4*)x)[idx];
    __half h0 = __float2half_rn(v.x), h1 = __float2half_rn(v.y);
    __half h2 = __float2half_rn(v.z), h3 = __float2half_rn(v.w);
    __half l0 = __float2half_rn(v.x - __half2float(h0));
    __half l1 = __float2half_rn(v.y - __half2float(h1));
    __half l2 = __float2half_rn(v.z - __half2float(h2));
    __half l3 = __float2half_rn(v.w - __half2float(h3));
    __half2 hp01 = __halves2half2(h0, h1), hp23 = __halves2half2(h2, h3);
    __half2 lp01 = __halves2half2(l0, l1), lp23 = __halves2half2(l2, l3);
    ((uint2*)g_Xh)[idx] = make_uint2(*(u32*)&hp01, *(u32*)&hp23);
    ((uint2*)g_Xl)[idx] = make_uint2(*(u32*)&lp01, *(u32*)&lp23);
}

// ---------------------------------------------------------------------------
// Kernel 1: prep — Â, vnr sums, init out with biases
// ---------------------------------------------------------------------------
__global__ void prep_kernel(const int* __restrict__ ei,
                            const float* __restrict__ vnr,
                            const float* __restrict__ avw, const float* __restrict__ avb,
                            const float* __restrict__ cvw, const float* __restrict__ cvb,
                            const float* __restrict__ afb, const float* __restrict__ cfb,
                            float* __restrict__ out, int out_size) {
    __shared__ float sA[10000];
    __shared__ float sdeg[N_NODES];
    const int t = threadIdx.x;  // 1024

    for (int i = t; i < 10000; i += 1024) sA[i] = 0.f;
    if (t < N_NODES) sdeg[t] = 0.f;
    __syncthreads();

    for (int e = t; e < N_EDGES; e += 1024) atomicAdd(&sdeg[ei[e]], 1.f);
    __syncthreads();
    if (t < N_NODES) {
        float d = sdeg[t];
        sdeg[t] = (d > 0.f) ? rsqrtf(fmaxf(d, 1.f)) : 0.f;
    }
    __syncthreads();
    for (int e = t; e < N_EDGES; e += 1024) {
        int s = ei[e];
        int d = ei[N_EDGES + e];
        atomicAdd(&sA[d * N_NODES + s], -sdeg[s] * sdeg[d]);
    }
    __syncthreads();
    for (int i = t; i < 10000; i += 1024) g_A[i] = sA[i];

    if (t < OUT_C) {
        float va = 0.f, vc = 0.f;
        #pragma unroll
        for (int i = 0; i < 3; i++) {
            float v = vnr[i];
            va += v * avw[i * OUT_C + t] + avb[i * OUT_C + t];
            vc += v * cvw[i * OUT_C + t] + cvb[i * OUT_C + t];
        }
        g_V[t] = va;
        g_V[OUT_C + t] = vc;
    }

    for (int j = t; j < out_size; j += 1024)
        out[j] = (j < 100) ? afb[j] : ((j == 100) ? cfb[0] : 0.f);
}

// ---------------------------------------------------------------------------
// Kernel 2: fp16 2-term tensor-core GEMM  (Y = (Xh + Xl) · fp16(W))
//   KTILE=64, double-buffered, occupancy 2, padded-M tile skipped
// ---------------------------------------------------------------------------
__global__ __launch_bounds__(GTHREADS, 2)
void gemm_mma(const float* __restrict__ aw,
              const float* __restrict__ cw) {
    extern __shared__ u32 smw[];
    const int t = threadIdx.x;
    const int lane = t & 31, wid = t >> 5;
    const int wm = wid >> 1, wn = wid & 1;
    const bool do_mt1 = (wm < 3);          // wm==3, mt==1 rows 112-127: all pad
    const int hk = blockIdx.y;
    const float* Wbase = ((hk >= 3) ? cw : aw) + (size_t)(hk % 3) * IN_C * OUT_C;

    int k0 = (int)(((long long)blockIdx.x * IN_C) / NSPLIT) & ~(KTILE - 1);
    int k1 = (int)(((long long)(blockIdx.x + 1) * IN_C) / NSPLIT) & ~(KTILE - 1);
    const int nch = (k1 - k0) / KTILE;

    for (int i = t; i < SMEM_W; i += GTHREADS) smw[i] = 0;

    float acc[2][4][4];
    #pragma unroll
    for (int mt = 0; mt < 2; mt++)
        #pragma unroll
        for (int nt = 0; nt < 4; nt++)
            #pragma unroll
            for (int q = 0; q < 4; q++) acc[mt][nt][q] = 0.f;

    // fragment smem byte addresses (stage-relative)
    const u32 sbase = smem_addr_u32(smw);
    const int t2 = lane >> 3, rr = lane & 7;
    const u32 a_off = (u32)(((wm * 32 + rr + (t2 & 1) * 8) * AROW_W + (t2 >> 1) * 4) * 4);
    const u32 b_off = (u32)(BHI_W * 4) +
                      (u32)(((wn * 32 + rr + (t2 >> 1) * 8) * AROW_W + (t2 & 1) * 4) * 4);

    uint2 xh[7], xl[7];
    float wr[15];

    // ---- preamble: load stage 0
    {
        int kb = k0;
        #pragma unroll
        for (int i = 0; i < 7; i++) {
            int idx = t + i * GTHREADS;
            if (idx < 1600) {
                int m = idx >> 4, q = idx & 15;
                size_t w = (size_t)m * (IN_C / 2) + (kb >> 1) + q * 2;
                xh[i] = *(const uint2*)(g_Xh + w);
                xl[i] = *(const uint2*)(g_Xl + w);
            }
        }
        #pragma unroll
        for (int i = 0; i < 15; i++) {
            int idx = t + i * GTHREADS;
            if (idx < KTILE * OUT_C) {
                int k = idx / OUT_C, ch = idx - k * OUT_C;
                wr[i] = Wbase[(size_t)(kb + k) * OUT_C + ch];
            }
        }
    }
    __syncthreads();   // zeroing done
    {
        u32* sb = smw;
        #pragma unroll
        for (int i = 0; i < 7; i++) {
            int idx = t + i * GTHREADS;
            if (idx < 1600) {
                int m = idx >> 4, q = idx & 15;
                int wofs = m * AROW_W + q * 2;
                *(uint2*)(sb + AHI_W + wofs) = xh[i];
                *(uint2*)(sb + ALO_W + wofs) = xl[i];
            }
        }
        #pragma unroll
        for (int i = 0; i < 15; i++) {
            int idx = t + i * GTHREADS;
            if (idx < KTILE * OUT_C) {
                int k = idx / OUT_C, ch = idx - k * OUT_C;
                ((__half*)(sb + BHI_W))[ch * 72 + k] = __float2half_rn(wr[i]);
            }
        }
    }
    __syncthreads();

    for (int c = 0; c < nch; c++) {
        const u32 stb = sbase + ((c & 1) ? STAGE_W * 4 : 0);
        const bool more = (c + 1 < nch);

        // ---- gmem prefetch for stage c+1
        if (more) {
            int kb = k0 + (c + 1) * KTILE;
            #pragma unroll
            for (int i = 0; i < 7; i++) {
                int idx = t + i * GTHREADS;
                if (idx < 1600) {
                    int m = idx >> 4, q = idx & 15;
                    size_t w = (size_t)m * (IN_C / 2) + (kb >> 1) + q * 2;
                    xh[i] = *(const uint2*)(g_Xh + w);
                    xl[i] = *(const uint2*)(g_Xl + w);
                }
            }
            #pragma unroll
            for (int i = 0; i < 15; i++) {
                int idx = t + i * GTHREADS;
                if (idx < KTILE * OUT_C) {
                    int k = idx / OUT_C, ch = idx - k * OUT_C;
                    wr[i] = Wbase[(size_t)(kb + k) * OUT_C + ch];
                }
            }
        }

        // ---- HMMA on stage c: 4 k16 steps, 2 terms
        #pragma unroll
        for (int kc = 0; kc < 4; kc++) {
            const u32 ko = kc * 32;
            u32 ah0[4], ah1[4], al0[4], al1[4];
            u32 b0[4], b1[4];
            LDSM4(ah0, stb + a_off + ko);
            if (do_mt1) LDSM4(ah1, stb + a_off + 2304 + ko);
            LDSM4(al0, stb + a_off + 18432 + ko);
            if (do_mt1) LDSM4(al1, stb + a_off + 18432 + 2304 + ko);
            LDSM4(b0, stb + b_off + ko);
            LDSM4(b1, stb + b_off + 2304 + ko);

            const u32* bh[4] = { b0, b0 + 2, b1, b1 + 2 };
            #pragma unroll
            for (int nt = 0; nt < 4; nt++) {
                mma16816(acc[0][nt], ah0, bh[nt]);
                mma16816(acc[0][nt], al0, bh[nt]);
                if (do_mt1) {
                    mma16816(acc[1][nt], ah1, bh[nt]);
                    mma16816(acc[1][nt], al1, bh[nt]);
                }
            }
        }

        // ---- convert+store stage c+1
        if (more) {
            u32* sb = smw + ((c + 1) & 1) * STAGE_W;
            #pragma unroll
            for (int i = 0; i < 7; i++) {
                int idx = t + i * GTHREADS;
                if (idx < 1600) {
                    int m = idx >> 4, q = idx & 15;
                    int wofs = m * AROW_W + q * 2;
                    *(uint2*)(sb + AHI_W + wofs) = xh[i];
                    *(uint2*)(sb + ALO_W + wofs) = xl[i];
                }
            }
            #pragma unroll
            for (int i = 0; i < 15; i++) {
                int idx = t + i * GTHREADS;
                if (idx < KTILE * OUT_C) {
                    int k = idx / OUT_C, ch = idx - k * OUT_C;
                    ((__half*)(sb + BHI_W))[ch * 72 + k] = __float2half_rn(wr[i]);
                }
            }
        }
        __syncthreads();
    }

    // ---- epilogue: atomicAdd into transposed Yt
    const int r = lane >> 2, cb = (lane & 3) * 2;
    float* Yg = g_Yt + hk * 60 * 100;
    #pragma unroll
    for (int mt = 0; mt < 2; mt++) {
        int row = wm * 32 + mt * 16 + r;
        #pragma unroll
        for (int nt = 0; nt < 4; nt++) {
            int col = wn * 32 + nt * 8 + cb;
            if (col < OUT_C) {
                if (row < N_NODES)     atomicAdd(Yg + col * 100 + row,     acc[mt][nt][0]);
                if (row + 8 < N_NODES) atomicAdd(Yg + col * 100 + row + 8, acc[mt][nt][2]);
            }
            if (col + 1 < OUT_C) {
                if (row < N_NODES)     atomicAdd(Yg + (col + 1) * 100 + row,     acc[mt][nt][1]);
                if (row + 8 < N_NODES) atomicAdd(Yg + (col + 1) * 100 + row + 8, acc[mt][nt][3]);
            }
        }
    }
}

// ---------------------------------------------------------------------------
// Kernel 3: emb columns; Â rows read as float4 straight from L2 (MLP 25)
//   emb[:,h,c] = tanh(y0 + Â(y1 + 2 Â y2) − y2 + b) + vnr
// ---------------------------------------------------------------------------
__global__ void emb3_kernel(const float* __restrict__ acb,
                            const float* __restrict__ ccb) {
    __shared__ float y0[100], y1[100], y2[104], zz[104];
    const int b = blockIdx.x, t = threadIdx.x;
    const int h = b / OUT_C, c = b - OUT_C * h;

    if (t < N_NODES) {
        y0[t] = g_Yt[(h * 180 + c) * 100 + t];
        y1[t] = g_Yt[(h * 180 + 60 + c) * 100 + t];
        y2[t] = g_Yt[(h * 180 + 120 + c) * 100 + t];
    }
    __syncthreads();

    if (t < N_NODES) {
        const float4* Ar = (const float4*)(g_A + t * 100);
        float a0 = 0.f, a1 = 0.f, a2 = 0.f, a3 = 0.f;
        #pragma unroll
        for (int q = 0; q < 25; q++) {
            float4 av = Ar[q];
            a0 = fmaf(av.x, y2[q * 4 + 0], a0);
            a1 = fmaf(av.y, y2[q * 4 + 1], a1);
            a2 = fmaf(av.z, y2[q * 4 + 2], a2);
            a3 = fmaf(av.w, y2[q * 4 + 3], a3);
        }
        zz[t] = fmaf(2.f, (a0 + a1) + (a2 + a3), y1[t]);
    }
    __syncthreads();

    if (t < N_NODES) {
        const float4* Ar = (const float4*)(g_A + t * 100);
        float a0 = 0.f, a1 = 0.f, a2 = 0.f, a3 = 0.f;
        #pragma unroll
        for (int q = 0; q < 25; q++) {
            float4 av = Ar[q];
            a0 = fmaf(av.x, zz[q * 4 + 0], a0);
            a1 = fmaf(av.y, zz[q * 4 + 1], a1);
            a2 = fmaf(av.z, zz[q * 4 + 2], a2);
            a3 = fmaf(av.w, zz[q * 4 + 3], a3);
        }
        float pre = y0[t] + (a0 + a1) + (a2 + a3) - y2[t] + (h ? ccb[c] : acb[c]);
        g_emb[h * 6000 + t * OUT_C + c] = tanhf(pre) + g_V[h * OUT_C + c];
    }
}

// ---------------------------------------------------------------------------
// Kernel 4: heads. 120 blocks x 128 threads, 50 rows each of the 6000-dot
// ---------------------------------------------------------------------------
__global__ void fc_kernel(const float* __restrict__ afw,
                          const float* __restrict__ cfw,
                          float* __restrict__ out, int out_size) {
    __shared__ float ea[50], ec[50];
    __shared__ float red[4];
    const int b = blockIdx.x, t = threadIdx.x;
    const int i0 = b * 50;

    if (t < 50) {
        ea[t] = g_emb[i0 + t];
        ec[t] = g_emb[6000 + i0 + t];
    }
    __syncthreads();

    if (t < 100) {
        float a0 = 0.f, a1 = 0.f;
        #pragma unroll 5
        for (int i = 0; i < 50; i += 2) {
            a0 = fmaf(ea[i],     afw[(size_t)(i0 + i) * 100 + t],     a0);
            a1 = fmaf(ea[i + 1], afw[(size_t)(i0 + i + 1) * 100 + t], a1);
        }
        atomicAdd(&out[t], a0 + a1);
    }

    float v = (t < 50) ? ec[t] * cfw[i0 + t] : 0.f;
    #pragma unroll
    for (int off = 16; off > 0; off >>= 1)
        v += __shfl_down_sync(0xffffffffu, v, off);
    if ((t & 31) == 0) red[t >> 5] = v;
    __syncthreads();
    if (t == 0 && out_size > 100)
        atomicAdd(&out[100], red[0] + red[1] + red[2] + red[3]);
}

// ---------------------------------------------------------------------------
// Launch
// ---------------------------------------------------------------------------
extern "C" void kernel_launch(void* const* d_in, const int* in_sizes, int n_in,
                              void* d_out, int out_size) {
    const float* x   = (const float*)d_in[0];
    const int*   ei  = (const int*)  d_in[1];
    const float* vnr = (const float*)d_in[2];
    const float* aw  = (const float*)d_in[3];
    const float* acb = (const float*)d_in[4];
    const float* cw  = (const float*)d_in[5];
    const float* ccb = (const float*)d_in[6];
    const float* avw = (const float*)d_in[7];
    const float* avb = (const float*)d_in[8];
    const float* cvw = (const float*)d_in[9];
    const float* cvb = (const float*)d_in[10];
    const float* afw = (const float*)d_in[11];
    const float* afb = (const float*)d_in[12];
    const float* cfw = (const float*)d_in[13];
    const float* cfb = (const float*)d_in[14];
    float* out = (float*)d_out;

    static int smem_set = 0;
    if (!smem_set) {
        cudaFuncSetAttribute(gemm_mma, cudaFuncAttributeMaxDynamicSharedMemorySize, SMEM_B);
        smem_set = 1;
    }

    xsplit_kernel<<<6400, 256>>>(x);
    prep_kernel<<<1, 1024>>>(ei, vnr, avw, avb, cvw, cvb, afb, cfb, out, out_size);
    gemm_mma<<<dim3(NSPLIT, 6), GTHREADS, SMEM_B>>>(aw, cw);
    emb3_kernel<<<120, 128>>>(acb, ccb);
    fc_kernel<<<120, 128>>>(afw, cfw, out, out_size);
}